// round 13
// baseline (speedup 1.0000x reference)
#include <cuda_runtime.h>
#include <cstdint>

// ItemEncoder R13: bulk-async ring + TWO stage-alternating consumer groups
// (4 warps/SMSP) with W staged in padded smem.
//   out[t,:] = M[ids[t],:] @ W^T + b ; 12800 tokens, D=2000, O=8.
//
//  - 1 CTA / SM, 544 threads = 17 warps:
//      warps 0-7  : group 0 (stages k%2==0)
//      warps 8-15 : group 1 (stages k%2==1)
//      warp 16    : producer (lane 0)
//  - W staged ONCE to smem by bulk copy: 8 rows x 8000 B at stride 8192
//    (pad 8000..8192 zeroed -> OOB quads 500..511 read 0).
//    Row stride 8192 = 0 mod 128 B -> XOR-rotated W LDS is bank-conflict-free.
//  - Ring: NBUF=5 x 32256 B (160 KB in flight). __syncthreads-free protocol:
//    full mbar (producer expect_tx + 4x bulk 8000 B), empty mbar count 1
//    arrived by the group's first thread after the group's named barrier.
//  - Compute per stage identical to R12: XOR-rotated acc so the butterfly
//    is selection-free (31 shfl + 31 add). Regs ~100 (W not in regs).
//  - Rationale: R12 proved the loop is latency-bound (issue 35%, removing
//    800 cyc of work changed nothing). Two groups interleave so one group's
//    epilogue/wait chain is hidden under the other's FMA stream.

static constexpr int NTOK  = 12800;
static constexpr int D     = 2000;
static constexpr int ROWB  = D * 4;          // 8000 B
static constexpr int QPR   = D / 4;          // 500
static constexpr int STOK  = 4;
static constexpr int NSTG  = NTOK / STOK;    // 3200
static constexpr int NTHR  = 544;
static constexpr int NGRP  = 256;            // threads per consumer group
static constexpr int NBUF  = 5;
static constexpr int STAGEB  = STOK * ROWB;  // 32000
static constexpr int BSTRIDE = 32256;        // +256 B zeroed pad
static constexpr int WROWB   = 8192;         // padded W row stride
static constexpr int SM_W    = 0;                        // 65536 B
static constexpr int SM_RING = 8 * WROWB;                // 65536
static constexpr int SM_RED  = SM_RING + NBUF * BSTRIDE; // 226816; 4096 B red
static constexpr int SM_MBAR = SM_RED + 4096;            // 230912
static constexpr int SM_TOT  = SM_MBAR + NBUF * 16 + 16; // +w mbar = 231008

__device__ __forceinline__ void ffma2(unsigned long long &acc,
                                      unsigned long long a,
                                      unsigned long long b) {
    asm("fma.rn.f32x2 %0, %1, %2, %0;" : "+l"(acc) : "l"(a), "l"(b));
}
__device__ __forceinline__ void mbar_init(uint32_t a, uint32_t cnt) {
    asm volatile("mbarrier.init.shared.b64 [%0], %1;" :: "r"(a), "r"(cnt) : "memory");
}
__device__ __forceinline__ void mbar_expect_tx(uint32_t a, uint32_t bytes) {
    asm volatile("mbarrier.arrive.expect_tx.shared.b64 _, [%0], %1;"
                 :: "r"(a), "r"(bytes) : "memory");
}
__device__ __forceinline__ void mbar_arrive(uint32_t a) {
    asm volatile("mbarrier.arrive.shared.b64 _, [%0];" :: "r"(a) : "memory");
}
__device__ __forceinline__ void mbar_wait(uint32_t a, uint32_t parity) {
    asm volatile(
        "{\n\t.reg .pred P;\n\t"
        "WL_%=:\n\t"
        "mbarrier.try_wait.parity.acquire.cta.shared::cta.b64 P, [%0], %1, 0x989680;\n\t"
        "@P bra WD_%=;\n\t"
        "bra WL_%=;\n\t"
        "WD_%=:\n\t}"
        :: "r"(a), "r"(parity) : "memory");
}
__device__ __forceinline__ void bulk_cp(uint32_t smem_dst, const void* gmem_src,
                                        uint32_t bytes, uint32_t mbar) {
    asm volatile(
        "cp.async.bulk.shared::cta.global.mbarrier::complete_tx::bytes "
        "[%0], [%1], %2, [%3];"
        :: "r"(smem_dst), "l"(gmem_src), "r"(bytes), "r"(mbar) : "memory");
}
__device__ __forceinline__ void bar_grp(int barid) {   // one consumer group
    asm volatile("bar.sync %0, %1;" :: "r"(barid), "n"(NGRP) : "memory");
}

__global__ void __launch_bounds__(NTHR, 1)
gather_proj_r13(const int*   __restrict__ ids,
                const float* __restrict__ M,
                const float* __restrict__ W,
                const float* __restrict__ bias,
                float*       __restrict__ out)
{
    extern __shared__ char smem[];
    const uint32_t smem_u32 = (uint32_t)__cvta_generic_to_shared(smem);
    const int tid  = threadIdx.x;
    const int lane = tid & 31;
    const int wid  = tid >> 5;
    const int lt   = lane >> 3;   // token rotation (2 bits)
    const int lo   = lane & 7;    // output rotation (3 bits)

    const int gridn  = gridDim.x;
    const int s0     = blockIdx.x;
    const int nLocal = (NSTG - s0 + gridn - 1) / gridn;

    auto fullb  = [&](int s) -> uint32_t { return smem_u32 + SM_MBAR + s * 16; };
    auto emptyb = [&](int s) -> uint32_t { return smem_u32 + SM_MBAR + s * 16 + 8; };
    const uint32_t wmbar = smem_u32 + SM_MBAR + NBUF * 16;

    // ---- init: mbarriers + zero pads (ring pads + W row pads) ----
    if (tid == 0) {
#pragma unroll
        for (int s = 0; s < NBUF; ++s) {
            mbar_init(fullb(s), 1);
            mbar_init(emptyb(s), 1);
        }
        mbar_init(wmbar, 1);
    }
    if (tid < NBUF * 16) {             // 5 x 256 B ring pads (quads 500..511)
        int b = tid >> 4, qq = tid & 15;
        *(float4*)(smem + SM_RING + b * BSTRIDE + STAGEB + qq * 16) =
            make_float4(0.f, 0.f, 0.f, 0.f);
    }
    if (tid >= 256 && tid < 256 + 8 * 12) {   // 8 x 192 B W pads
        int j = tid - 256;                    // 96 float4s
        int r = j / 12, qq = j % 12;
        *(float4*)(smem + SM_W + r * WROWB + ROWB + qq * 16) =
            make_float4(0.f, 0.f, 0.f, 0.f);
    }
    __syncthreads();                   // mbarriers + pads visible

    if (wid == 16) {
        // ================= producer (lane 0) =================
        if (lane == 0) {
            const char* Mb = (const char*)M;
            const char* Wb = (const char*)W;
            // one-time: stage W into padded smem rows
            mbar_expect_tx(wmbar, 8 * ROWB);
#pragma unroll
            for (int o = 0; o < 8; ++o)
                bulk_cp(smem_u32 + SM_W + o * WROWB, Wb + (size_t)o * ROWB,
                        ROWB, wmbar);

            int4 nid = __ldg((const int4*)ids + s0);   // stage 0 ids
            for (int k = 0; k < nLocal; ++k) {
                const int slot = k % NBUF;
                mbar_wait(emptyb(slot), ((k / NBUF) & 1) ^ 1);
                const uint32_t dst = smem_u32 + SM_RING + slot * BSTRIDE;
                mbar_expect_tx(fullb(slot), STAGEB);
                bulk_cp(dst,            Mb + (size_t)nid.x * ROWB, ROWB, fullb(slot));
                bulk_cp(dst + ROWB,     Mb + (size_t)nid.y * ROWB, ROWB, fullb(slot));
                bulk_cp(dst + 2 * ROWB, Mb + (size_t)nid.z * ROWB, ROWB, fullb(slot));
                bulk_cp(dst + 3 * ROWB, Mb + (size_t)nid.w * ROWB, ROWB, fullb(slot));
                if (k + 1 < nLocal)    // ids pipelined one stage ahead
                    nid = __ldg((const int4*)ids + (s0 + (k + 1) * gridn));
            }
        }
        return;
    }

    // ================= consumers: group g = wid>>3, warp-in-group p = wid&7 ====
    const int g  = wid >> 3;
    const int p  = wid & 7;
    const float bval = __ldg(bias + (lane & 7));
    float* red = (float*)(smem + SM_RED);

    mbar_wait(wmbar, 0);               // W staged (one-time)

    for (int k = g; k < nLocal; k += 2) {
        const int slot = k % NBUF;
        mbar_wait(fullb(slot), (k / NBUF) & 1);
        const char* buf = smem + SM_RING + slot * BSTRIDE;

        unsigned long long acc[4][8];
#pragma unroll
        for (int t = 0; t < 4; ++t)
#pragma unroll
            for (int o = 0; o < 8; ++o) acc[t][o] = 0ull;

#pragma unroll
        for (int it = 0; it < 2; ++it) {
            const int q = p * 64 + it * 32 + lane;   // 500..511: pad data, W=0
            // token rows XOR-rotated by lt (conflict-free: same lt per phase)
            ulonglong2 v[4];
#pragma unroll
            for (int t = 0; t < 4; ++t)
                v[t] = *(const ulonglong2*)(buf + (t ^ lt) * ROWB + q * 16);
#pragma unroll
            for (int o = 0; o < 8; ++o) {
                // W rows XOR-rotated by lo from padded smem (OOB quads = 0)
                const ulonglong2 wv = *(const ulonglong2*)
                    (smem + SM_W + (o ^ lo) * WROWB + q * 16);
#pragma unroll
                for (int t = 0; t < 4; ++t) {
                    ffma2(acc[t][o], v[t].x, wv.x);
                    ffma2(acc[t][o], v[t].y, wv.y);
                }
            }
        }
        // acc slot j = t*8+o holds partial of value j^lane

        // ---- collapse f32x2 halves -> 32 scalars ----
        float cur[32];
#pragma unroll
        for (int t = 0; t < 4; ++t)
#pragma unroll
            for (int o = 0; o < 8; ++o) {
                const unsigned long long a = acc[t][o];
                cur[t * 8 + o] = __uint_as_float((unsigned)a) +
                                 __uint_as_float((unsigned)(a >> 32));
            }

        // ---- selection-free butterfly: 31 shfl + 31 add ----
#pragma unroll
        for (int off = 16; off >= 1; off >>= 1) {
#pragma unroll
            for (int j = 0; j < off; ++j)
                cur[j] += __shfl_xor_sync(0xffffffffu, cur[j + off], off);
        }
        // lane l: cur[0] = this warp's total of value l (token l>>3, out l&7)

        // red area: [group][stage parity within group][256]
        float* redk = red + g * 512 + ((k >> 1) & 1) * 256;
        redk[p * 32 + lane] = cur[0];
        bar_grp(1 + g);                // group's red visible; group's buf reads done
        if (tid == g * NGRP) mbar_arrive(emptyb(slot));   // single release

        if (p == 0) {
            float s = bval;
#pragma unroll
            for (int w8 = 0; w8 < 8; ++w8) s += redk[w8 * 32 + lane];
            out[(size_t)(s0 + k * gridn) * 32 + lane] = s;
        }
    }
}

extern "C" void kernel_launch(void* const* d_in, const int* in_sizes, int n_in,
                              void* d_out, int out_size) {
    const int*   ids  = (const int*)  d_in[0];
    const float* M    = (const float*)d_in[1];
    const float* W    = (const float*)d_in[2];
    const float* bias = (const float*)d_in[3];
    float*       out  = (float*)d_out;

    cudaFuncSetAttribute(gather_proj_r13,
                         cudaFuncAttributeMaxDynamicSharedMemorySize, SM_TOT);

    int nsm = 148;
    cudaDeviceGetAttribute(&nsm, cudaDevAttrMultiProcessorCount, 0);

    gather_proj_r13<<<nsm, NTHR, SM_TOT>>>(ids, M, W, bias, out);
}